// round 17
// baseline (speedup 1.0000x reference)
#include <cuda_runtime.h>
#include <cstdint>

#define CTC_V  128
#define NEG2   (-1.0e30f)
#define KS     8                 // time steps per block (== halo depth)
#define UW     (32 - KS)         // useful lanes per warp (24)
#define NW     11
#define NTHR   (NW * 32)         // 352
#define TMAX   1024
#define BMAX   64
#define TP     (TMAX + KS)       // padded time extent
#define PPAD   258

// Scratch (padded in t; pad stays 0 from zero-init, never written).
__device__ float  g_blank[BMAX * TP];
__device__ float  g_lse  [BMAX * TP];
__device__ float2 g_alpha[BMAX * PPAD];
__device__ float2 g_beta [BMAX * PPAD];
__device__ int    g_cnt  [BMAX];

__device__ __forceinline__ float ex2(float x) {
    float y; asm("ex2.approx.ftz.f32 %0, %1;" : "=f"(y) : "f"(x)); return y;
}
__device__ __forceinline__ float lg2(float x) {
    float y; asm("lg2.approx.ftz.f32 %0, %1;" : "=f"(y) : "f"(x)); return y;
}
// Exact renorm: fold R's exponent into M; R -> [1,2). Zero/denorm R safe.
__device__ __forceinline__ void renorm(float& M, float& R) {
    unsigned u = __float_as_uint(R);
    unsigned eb = u >> 23;
    int e = (eb != 0u) ? (int)eb - 127 : 0;
    R = __uint_as_float(u - ((unsigned)e << 23));
    M += (float)e;
}

// ---------------------------------------------------------------------------
// Kernel 1: per-(t,b) log2-sum-exp (2 rows per warp). Writes ONLY lse+blank
// (0.5 MB); acts stay L2-resident for kernel 2. Also zeroes arrival counters.
// ---------------------------------------------------------------------------
__global__ void lse_k(const float* __restrict__ acts, int rows, int T, int B) {
    if (blockIdx.x == 0 && threadIdx.x < BMAX) g_cnt[threadIdx.x] = 0;
    int gw   = (blockIdx.x * blockDim.x + threadIdx.x) >> 5;
    int lane = threadIdx.x & 31;
    int r0 = gw * 2;
    if (r0 >= rows) return;
    int r1 = r0 + 1;                       // rows = T*B is even
    const float L2E = 1.4426950408889634f;
    float4 va = reinterpret_cast<const float4*>(acts)[(size_t)r0 * 32 + lane];
    float4 vb = reinterpret_cast<const float4*>(acts)[(size_t)r1 * 32 + lane];
    float a0 = va.x * L2E, a1 = va.y * L2E, a2 = va.z * L2E, a3 = va.w * L2E;
    float b0 = vb.x * L2E, b1 = vb.y * L2E, b2 = vb.z * L2E, b3 = vb.w * L2E;
    float ma = fmaxf(fmaxf(a0, a1), fmaxf(a2, a3));
    float mb = fmaxf(fmaxf(b0, b1), fmaxf(b2, b3));
#pragma unroll
    for (int o = 16; o; o >>= 1) {
        ma = fmaxf(ma, __shfl_xor_sync(0xffffffffu, ma, o));
        mb = fmaxf(mb, __shfl_xor_sync(0xffffffffu, mb, o));
    }
    float sa = ex2(a0 - ma) + ex2(a1 - ma) + ex2(a2 - ma) + ex2(a3 - ma);
    float sb = ex2(b0 - mb) + ex2(b1 - mb) + ex2(b2 - mb) + ex2(b3 - mb);
#pragma unroll
    for (int o = 16; o; o >>= 1) {
        sa += __shfl_xor_sync(0xffffffffu, sa, o);
        sb += __shfl_xor_sync(0xffffffffu, sb, o);
    }
    float la = lg2(sa) + ma, lb = lg2(sb) + mb;
    if (lane == 0) {
        int t0 = r0 / B, bb0 = r0 - t0 * B;
        int t1 = r1 / B, bb1 = r1 - t1 * B;
        g_blank[bb0 * TP + t0] = a0 - la;
        g_lse  [bb0 * TP + t0] = la;
        g_blank[bb1 * TP + t1] = b0 - lb;
        g_lse  [bb1 * TP + t1] = lb;
    }
}

// ---------------------------------------------------------------------------
// Kernel 2: fused forward+backward (M,R) recursion + fused combine.
// 2 CTAs per batch: even = forward to t* = Tlen/2, odd = backward to t*.
// Label emits formed on the fly from raw acts (L2-warm) + broadcast lse.
// Second-arriving CTA per batch computes the loss and atomicAdds into out.
// ---------------------------------------------------------------------------
__global__ __launch_bounds__(NTHR, 1) void ctc_fb_k(
    float* __restrict__ out, const float* __restrict__ acts,
    const int* __restrict__ labels, const int* __restrict__ act_lens,
    const int* __restrict__ label_lens, int T, int B, int L)
{
    __shared__ __align__(16) float4 shA[2][NW * UW + KS];
    __shared__ int s_done;

    const int V = CTC_V;
    const int cta = blockIdx.x;
    const int b = cta >> 1;
    const bool bwd = (cta & 1);
    const int P = L + 1;
    const int tid = threadIdx.x, lane = tid & 31, w = tid >> 5;
    const float L2E = 1.4426950408889634f;

    int Tlen = act_lens[b];
    if (Tlen > T) Tlen = T;
    if (Tlen < 1) Tlen = 1;
    const int tstar = Tlen >> 1;

    const float* __restrict__ pb = g_blank + (size_t)b * TP;
    const float* __restrict__ ps = g_lse   + (size_t)b * TP;
    const size_t rstr = (size_t)B * V;

    if (!bwd) {
        // ================== FORWARD (Te = tstar+1) ==================
        const int Te = tstar + 1;
        const int p = w * UW + lane - KS;
        const bool in0 = ((unsigned)p < (unsigned)P);
        const bool in1 = ((unsigned)p < (unsigned)L);
        const int  lab   = in1 ? labels[b * L + p] : 0;
        const bool allow = in1 && (p >= 1) && (lab != labels[b * L + p - 1]);
        const bool useful = (lane >= KS) && in0;
        const float* __restrict__ pl = acts + (size_t)b * V + lab;

        float M0 = NEG2, R0 = 1.0f, M1 = NEG2, R1 = 1.0f;
        if (p == 0) {
            M0 = __ldg(pb);
            if (in1) M1 = fmaf(__ldg(pl), L2E, -__ldg(ps));
        }
        if (useful) shA[0][p] = make_float4(M0, R0, M1, R1);

        float eb[KS], el[KS];
#pragma unroll
        for (int j = 0; j < KS; ++j) {
            int t = 1 + j;
            int tc = t < Tlen ? t : Tlen - 1;
            eb[j] = __ldg(pb + t);
            el[j] = fmaf(__ldg(pl + (size_t)tc * rstr), L2E, -__ldg(ps + t));
        }
        __syncthreads();

        const int NB     = (Te - 1 + KS - 1) / KS;
        const int NBfull = NB > 0 ? NB - 1 : 0;

        for (int blk = 0; blk < NB; ++blk) {
            {
                float4 v = in0 ? shA[blk & 1][p] : make_float4(NEG2, 1.f, NEG2, 1.f);
                M0 = v.x; R0 = v.y;
                M1 = in1 ? v.z : NEG2;
                R1 = in1 ? v.w : 1.0f;
            }
            float nb_[KS], nl_[KS];
            {
                int tb = (blk + 1) * KS + 1;
#pragma unroll
                for (int j = 0; j < KS; ++j) {
                    int t = tb + j;                    // padded: lse/blank safe
                    int tc = t < Tlen ? t : Tlen - 1;  // acts clamped
                    nb_[j] = __ldg(pb + t);
                    nl_[j] = fmaf(__ldg(pl + (size_t)tc * rstr), L2E, -__ldg(ps + t));
                }
            }
            if (blk < NBfull) {
#pragma unroll
                for (int j = 0; j < KS; ++j) {
                    float zM = __shfl_up_sync(0xffffffffu, M1, 1);
                    float zR = __shfl_up_sync(0xffffffffu, R1, 1);
                    float mC = fmaxf(fmaxf(M0, M1), zM);
                    float x0 = ex2(M0 - mC);
                    float x1 = ex2(M1 - mC);
                    float xz = ex2(zM - mC);
                    float R0x0 = R0 * x0;
                    float Rzxz = zR * xz;
                    float Rzg  = allow ? Rzxz : 0.0f;
                    R0 = R0x0 + Rzxz;
                    R1 = fmaf(R1, x1, R0x0 + Rzg);
                    M0 = mC + eb[j];
                    M1 = mC + el[j];
                }
            } else {
#pragma unroll
                for (int j = 0; j < KS; ++j) {
                    int t = blk * KS + 1 + j;
                    float zM = __shfl_up_sync(0xffffffffu, M1, 1);
                    float zR = __shfl_up_sync(0xffffffffu, R1, 1);
                    float d   = zM - M0;
                    float x   = ex2(0.0f - fabsf(d));
                    float Mb  = fmaxf(M0, zM);
                    float Rhi = (d > 0.0f) ? zR : R0;
                    float Rlo = (d > 0.0f) ? R0 : zR;
                    float nM0 = Mb + eb[j];
                    float nR0 = fmaf(Rlo, x, Rhi);
                    float Mq  = allow ? zM : NEG2;
                    float m1  = fmaxf(fmaxf(M1, M0), Mq);
                    float nR1 = fmaf(R1, ex2(M1 - m1),
                                fmaf(R0, ex2(M0 - m1), zR * ex2(Mq - m1)));
                    float nM1 = m1 + el[j];
                    bool u = (t < Te);
                    M0 = (u && in0) ? nM0 : M0;  R0 = (u && in0) ? nR0 : R0;
                    M1 = (u && in1) ? nM1 : M1;  R1 = (u && in1) ? nR1 : R1;
                }
            }
            renorm(M0, R0); renorm(M1, R1);
            if (useful) shA[(blk + 1) & 1][p] = make_float4(M0, R0, M1, R1);
            __syncthreads();
#pragma unroll
            for (int j = 0; j < KS; ++j) { eb[j] = nb_[j]; el[j] = nl_[j]; }
        }

        if (useful) {
            float f0 = in0 ? (M0 + lg2(R0)) : NEG2;
            float f1 = in1 ? (M1 + lg2(R1)) : NEG2;
            g_alpha[(size_t)b * PPAD + p] = make_float2(f0, f1);
        }
    } else {
        // ================== BACKWARD (to t*) ==================
        const int q = w * UW + lane;               // halo = high lanes
        const bool in0 = ((unsigned)q < (unsigned)P);
        const bool in1 = ((unsigned)q < (unsigned)L);
        const int  lab = in1 ? labels[b * L + q] : 0;
        bool allowD = false;
        if (in1 && (q + 1 < L)) allowD = (labels[b * L + q + 1] != lab);
        const bool useful = (lane < UW) && in0;
        const float* __restrict__ pl = acts + (size_t)b * V + lab;

        int Lb = label_lens[b];
        if (Lb > L) Lb = L;
        if (Lb < 0) Lb = 0;

        float M0 = (q == Lb)     ? 0.0f : NEG2;  float R0 = 1.0f;
        float M1 = (q == Lb - 1) ? 0.0f : NEG2;  float R1 = 1.0f;
        if (useful) shA[0][q] = make_float4(M0, R0, M1, R1);

        const int ns = Tlen - 1 - tstar;

        float eb[KS], el[KS];
#pragma unroll
        for (int j = 0; j < KS; ++j) {
            int te = Tlen - 1 - j; te = te < 0 ? 0 : te;
            eb[j] = __ldg(pb + te);
            el[j] = fmaf(__ldg(pl + (size_t)te * rstr), L2E, -__ldg(ps + te));
        }
        __syncthreads();

        const int NB     = (ns + KS - 1) / KS;
        const int NBfull = NB > 0 ? NB - 1 : 0;

        for (int blk = 0; blk < NB; ++blk) {
            {
                float4 v = shA[blk & 1][q];
                M0 = in0 ? v.x : NEG2;  R0 = in0 ? v.y : 1.0f;
                M1 = in1 ? v.z : NEG2;  R1 = in1 ? v.w : 1.0f;
            }
            float nb_[KS], nl_[KS];
            {
                int kb = (blk + 1) * KS;
#pragma unroll
                for (int j = 0; j < KS; ++j) {
                    int te = Tlen - 1 - (kb + j); te = te < 0 ? 0 : te;
                    nb_[j] = __ldg(pb + te);
                    nl_[j] = fmaf(__ldg(pl + (size_t)te * rstr), L2E, -__ldg(ps + te));
                }
            }
            if (blk < NBfull) {
#pragma unroll
                for (int j = 0; j < KS; ++j) {
                    float vb = M0 + eb[j];
                    float vl = M1 + el[j];
                    float db  = __shfl_down_sync(0xffffffffu, vb, 1);
                    float dRb = __shfl_down_sync(0xffffffffu, R0, 1);
                    float dl  = __shfl_down_sync(0xffffffffu, vl, 1);
                    float dRl = __shfl_down_sync(0xffffffffu, R1, 1);
                    float mC = fmaxf(fmaxf(vb, vl), fmaxf(db, dl));
                    float xb  = ex2(vb - mC);
                    float xl  = ex2(vl - mC);
                    float xdb = ex2(db - mC);
                    float xdl = ex2(dl - mC);
                    float tb  = R0 * xb;
                    float t1  = R1 * xl;
                    float tdb = dRb * xdb;
                    float tdl = allowD ? dRl * xdl : 0.0f;
                    R0 = tb + t1;
                    R1 = t1 + tdb + tdl;
                    M0 = mC; M1 = mC;
                }
            } else {
#pragma unroll
                for (int j = 0; j < KS; ++j) {
                    int k = blk * KS + j;
                    float vb = M0 + eb[j];
                    float vl = M1 + el[j];
                    float db  = __shfl_down_sync(0xffffffffu, vb, 1);
                    float dRb = __shfl_down_sync(0xffffffffu, R0, 1);
                    float dl  = __shfl_down_sync(0xffffffffu, vl, 1);
                    float dRl = __shfl_down_sync(0xffffffffu, R1, 1);
                    float mC = fmaxf(fmaxf(vb, vl), fmaxf(db, dl));
                    float xb  = ex2(vb - mC);
                    float xl  = ex2(vl - mC);
                    float xdb = ex2(db - mC);
                    float xdl = ex2(dl - mC);
                    float tb  = R0 * xb;
                    float t1  = R1 * xl;
                    float tdb = dRb * xdb;
                    float tdl = allowD ? dRl * xdl : 0.0f;
                    float nR0 = tb + t1;
                    float nR1 = t1 + tdb + tdl;
                    bool u = (k < ns);
                    M0 = (u && in0) ? mC  : M0;  R0 = (u && in0) ? nR0 : R0;
                    M1 = (u && in1) ? mC  : M1;  R1 = (u && in1) ? nR1 : R1;
                }
            }
            renorm(M0, R0); renorm(M1, R1);
            if (useful) shA[(blk + 1) & 1][q] = make_float4(M0, R0, M1, R1);
            __syncthreads();
#pragma unroll
            for (int j = 0; j < KS; ++j) { eb[j] = nb_[j]; el[j] = nl_[j]; }
        }

        if (useful) {
            float f0 = in0 ? (M0 + lg2(R0)) : NEG2;
            float f1 = in1 ? (M1 + lg2(R1)) : NEG2;
            g_beta[(size_t)b * PPAD + q] = make_float2(f0, f1);
        }
    }

    // ================== FUSED COMBINE (second arriver) ==================
    __threadfence();        // make this thread's global writes visible
    __syncthreads();
    if (tid == 0) s_done = atomicAdd(&g_cnt[b], 1);
    __syncthreads();
    if (s_done == 1 && w == 0) {
        __threadfence();    // acquire side
        float m = -3.0e38f, r = 0.0f;
        for (int p = lane; p < P; p += 32) {
            float2 fa = g_alpha[(size_t)b * PPAD + p];
            float2 fb = g_beta [(size_t)b * PPAD + p];
            float v0 = fa.x + fb.x;
            float v1 = fa.y + fb.y;
            float nm = fmaxf(m, v0);
            r = r * ex2(m - nm) + ex2(v0 - nm); m = nm;
            nm = fmaxf(m, v1);
            r = r * ex2(m - nm) + ex2(v1 - nm); m = nm;
        }
#pragma unroll
        for (int o = 16; o; o >>= 1) {
            float om  = __shfl_xor_sync(0xffffffffu, m, o);
            float orr = __shfl_xor_sync(0xffffffffu, r, o);
            float nm = fmaxf(m, om);
            r = r * ex2(m - nm) + orr * ex2(om - nm);
            m = nm;
        }
        if (lane == 0)
            atomicAdd(out, -(m + lg2(r)) * 0.69314718055994530942f);
    }
}

// ---------------------------------------------------------------------------
extern "C" void kernel_launch(void* const* d_in, const int* in_sizes, int n_in,
                              void* d_out, int out_size)
{
    const float* acts      = (const float*)d_in[0];
    const int*   labels    = (const int*)d_in[1];
    const int*   act_lens  = (const int*)d_in[2];
    const int*   label_len = (const int*)d_in[3];

    int B = in_sizes[2];
    int L = in_sizes[1] / B;
    int V = CTC_V;
    int T = in_sizes[0] / (B * V);

    cudaMemsetAsync(d_out, 0, sizeof(float));

    int rows = T * B;
    int nwarp = (rows + 1) / 2;
    lse_k<<<(nwarp + 7) / 8, 256>>>(acts, rows, T, B);

    ctc_fb_k<<<2 * B, NTHR>>>((float*)d_out, acts, labels, act_lens, label_len,
                              T, B, L);
}